// round 8
// baseline (speedup 1.0000x reference)
#include <cuda_runtime.h>
#include <cstdint>

// ---------------- problem constants ----------------
#define B_    8
#define K_    8
#define C_    256
#define L_    4096
#define TOPK  4
#define KTOT  1024
#define BM    128
#define BN    128
#define BK    32
#define NCHUNK (KTOT / BK)     // 32
#define NSTAGE 4

// ---------------- smem layout (bytes from dynamic smem base) ----------------
// bf16 tiles (double buffered):
// A: 128 rows x 32 bf16, padded row stride 40 bf16 = 80 B (5x16B odd -> ldmatrix conflict-free)
// B: 32 rows (k) x 128 bf16 (n), padded stride 136 bf16 = 272 B (17x16B odd)
#define ASTRIDE_B 80
#define BSTRIDE_B 272
#define ATILE_B   (128 * ASTRIDE_B)           // 10240
#define BTILE_B   (32 * BSTRIDE_B)            // 8704
#define BUF_B     (2 * ATILE_B + 2 * BTILE_B) // 37888
#define OFF_AHI(buf) ((buf) * BUF_B + 0)
#define OFF_ALO(buf) ((buf) * BUF_B + ATILE_B)
#define OFF_BHI(buf) ((buf) * BUF_B + 2 * ATILE_B)
#define OFF_BLO(buf) ((buf) * BUF_B + 2 * ATILE_B + BTILE_B)
// fp32 cp.async stage ring: per stage A(16KB linear f-indexed) + B(16KB)
#define OFF_STAGE    (2 * BUF_B)               // 75776
#define STAGE_B      32768
#define OFF_STA(s)   (OFF_STAGE + (s) * STAGE_B)
#define OFF_STB(s)   (OFF_STAGE + (s) * STAGE_B + 16384)
#define SMEM_DYN     (OFF_STAGE + NSTAGE * STAGE_B)   // 206848

// ---------------- helpers ----------------
__device__ __forceinline__ uint32_t smem_u32(const void* p) {
    uint32_t a;
    asm("{ .reg .u64 t; cvta.to.shared.u64 t, %1; cvt.u32.u64 %0, t; }" : "=r"(a) : "l"(p));
    return a;
}

// split x -> (hi = truncate-to-bf16, lo = rn-bf16(x - hi)); pack two elements
__device__ __forceinline__ void split_pair(float x0, float x1,
                                           uint32_t& hi, uint32_t& lo) {
    uint32_t u0 = __float_as_uint(x0), u1 = __float_as_uint(x1);
    hi = __byte_perm(u0, u1, 0x7632);   // {bf16(x1)|bf16(x0)} truncated
    float l0 = x0 - __uint_as_float(u0 & 0xFFFF0000u);
    float l1 = x1 - __uint_as_float(u1 & 0xFFFF0000u);
    asm("cvt.rn.bf16x2.f32 %0, %1, %2;" : "=r"(lo) : "f"(l1), "f"(l0));
}

#define STS64(addr, r0, r1) \
    asm volatile("st.shared.v2.b32 [%0], {%1, %2};" :: "r"(addr), "r"(r0), "r"(r1) : "memory")
#define LDS128F(v, addr) \
    asm volatile("ld.shared.v4.f32 {%0,%1,%2,%3}, [%4];" \
                 : "=f"((v).x), "=f"((v).y), "=f"((v).z), "=f"((v).w) : "r"(addr))
#define CP_ASYNC16(saddr, gptr) \
    asm volatile("cp.async.cg.shared.global [%0], [%1], 16;" :: "r"(saddr), "l"(gptr) : "memory")
#define CP_COMMIT() asm volatile("cp.async.commit_group;" ::: "memory")
#define CP_WAIT3()  asm volatile("cp.async.wait_group 3;" ::: "memory")

__device__ __forceinline__ void ldsm_x4(uint32_t addr, uint32_t* r) {
    asm volatile("ldmatrix.sync.aligned.m8n8.x4.shared.b16 {%0,%1,%2,%3}, [%4];"
                 : "=r"(r[0]), "=r"(r[1]), "=r"(r[2]), "=r"(r[3]) : "r"(addr));
}
__device__ __forceinline__ void ldsm_x2_trans(uint32_t addr, uint32_t* r) {
    asm volatile("ldmatrix.sync.aligned.m8n8.x2.trans.shared.b16 {%0,%1}, [%2];"
                 : "=r"(r[0]), "=r"(r[1]) : "r"(addr));
}
__device__ __forceinline__ void mma_bf16(float* c, const uint32_t* a, const uint32_t* bfr) {
    asm volatile(
        "mma.sync.aligned.m16n8k16.row.col.f32.bf16.bf16.f32 "
        "{%0,%1,%2,%3}, {%4,%5,%6,%7}, {%8,%9}, {%0,%1,%2,%3};"
        : "+f"(c[0]), "+f"(c[1]), "+f"(c[2]), "+f"(c[3])
        : "r"(a[0]), "r"(a[1]), "r"(a[2]), "r"(a[3]), "r"(bfr[0]), "r"(bfr[1]));
}

// ---------------- routing globals ----------------
__device__ int   g_sel[B_][TOPK];
__device__ float g_w[B_][TOPK];
__device__ float g_bias[B_][C_];

__global__ void prep_kernel(const float* __restrict__ scores,
                            const float* __restrict__ expert_b) {
    __shared__ int   s_sel[B_][TOPK];
    __shared__ float s_w[B_][TOPK];
    const int tid = threadIdx.x;
    if (tid < B_) {
        const int b = tid;
        float sc[K_]; bool used[K_];
#pragma unroll
        for (int k = 0; k < K_; k++) { sc[k] = scores[b * K_ + k]; used[k] = false; }
        float sum = 0.f;
#pragma unroll
        for (int j = 0; j < TOPK; j++) {
            int best = 0; float bv = -3.402823466e+38f;
#pragma unroll
            for (int k = 0; k < K_; k++)
                if (!used[k] && sc[k] > bv) { bv = sc[k]; best = k; }  // ties -> lower idx
            used[best] = true; s_sel[b][j] = best; s_w[b][j] = bv; sum += bv;
        }
        const float inv = 1.f / (sum + 1e-8f);
#pragma unroll
        for (int j = 0; j < TOPK; j++) {
            s_w[b][j] *= inv; g_sel[b][j] = s_sel[b][j]; g_w[b][j] = s_w[b][j];
        }
    }
    __syncthreads();
    for (int idx = tid; idx < B_ * C_; idx += blockDim.x) {
        const int b = idx / C_, d = idx % C_;
        float acc = 0.f;
#pragma unroll
        for (int j = 0; j < TOPK; j++)
            acc += s_w[b][j] * expert_b[s_sel[b][j] * C_ + d];
        g_bias[b][d] = acc;
    }
}

// ---------------------------------------------------------------------------
// Tensor-core MoE GEMM via mma.sync (bf16 hi/lo split, 3 terms, fp32 accum),
// cp.async 4-stage fp32 ring -> smem convert -> bf16 double buffer -> HMMA.
// out[b](256x4096) = [w_j * W_sel_j](256x1024) @ gathered_xs(1024x4096) + bias
// ---------------------------------------------------------------------------
__global__ __launch_bounds__(256, 1)
void moe_mma_kernel(const float* __restrict__ xs,
                    const float* __restrict__ expert_w,
                    float* __restrict__ out) {
    extern __shared__ char smem[];
    const uint32_t sb = smem_u32(smem);

    const int tid  = threadIdx.x;
    const int wid  = tid >> 5;
    const int lane = tid & 31;
    const int b    = blockIdx.z;
    const int m0   = blockIdx.y * BM;
    const int n0   = blockIdx.x * BN;

    int   sel[TOPK];
    float wv[TOPK];
#pragma unroll
    for (int j = 0; j < TOPK; j++) { sel[j] = g_sel[b][j]; wv[j] = g_w[b][j]; }

    // warp tile: 64 (m) x 32 (n)
    const int wm = wid >> 2, wn = wid & 3;
    const int m_base = wm * 64, n_base = wn * 32;

    float acc[4][4][4];
#pragma unroll
    for (int mi = 0; mi < 4; mi++)
#pragma unroll
        for (int ni = 0; ni < 4; ni++)
#pragma unroll
            for (int r = 0; r < 4; r++) acc[mi][ni][r] = 0.f;

    // ldmatrix address components
    const int lr = lane & 7;
    const int lg = lane >> 3;
    const int a_r_off = (lg & 1) * 8 + lr;
    const int a_c_off = (lg >> 1) * 8;
    const int b_r_off = (lg & 1) * 8 + lr;

    // issue the cp.async group for chunk ck into stage s (f-indexed linear layout)
    auto issue_cp = [&](int ck, int s) {
        const int j  = ck >> 3;
        const int c0 = (ck & 7) * BK;
        const float* asrc = expert_w + ((size_t)sel[j] * C_) * C_ + c0;
        const float* bsrc = xs + (((size_t)b * K_ + sel[j]) * C_ + c0) * L_ + n0;
        const uint32_t sta = sb + OFF_STA(s), stb = sb + OFF_STB(s);
#pragma unroll
        for (int q = 0; q < 4; q++) {
            int f = q * 256 + tid;
            int r = f >> 3, c4 = f & 7;
            CP_ASYNC16(sta + f * 16, asrc + (size_t)(m0 + r) * C_ + c4 * 4);
        }
#pragma unroll
        for (int q = 0; q < 4; q++) {
            int f = q * 256 + tid;
            int r = f >> 5, c4 = f & 31;
            CP_ASYNC16(stb + f * 16, bsrc + (size_t)r * L_ + c4 * 4);
        }
        CP_COMMIT();
    };

    // convert stage s (fp32) -> bf16 buffer buf (thread converts exactly what it copied)
    auto convert = [&](int ck, int s, int buf) {
        const float wj = wv[ck >> 3];
        const uint32_t sta = sb + OFF_STA(s), stb = sb + OFF_STB(s);
        const uint32_t ah = sb + OFF_AHI(buf), al = sb + OFF_ALO(buf);
        const uint32_t bh = sb + OFF_BHI(buf), bl = sb + OFF_BLO(buf);
#pragma unroll
        for (int q = 0; q < 4; q++) {
            int f = q * 256 + tid;
            int r = f >> 3, c4 = f & 7;
            float4 v; LDS128F(v, sta + f * 16);
            uint32_t h0, l0, h1, l1;
            split_pair(v.x * wj, v.y * wj, h0, l0);
            split_pair(v.z * wj, v.w * wj, h1, l1);
            uint32_t addr = r * ASTRIDE_B + c4 * 8;
            STS64(ah + addr, h0, h1);
            STS64(al + addr, l0, l1);
        }
#pragma unroll
        for (int q = 0; q < 4; q++) {
            int f = q * 256 + tid;
            int r = f >> 5, c4 = f & 31;
            float4 v; LDS128F(v, stb + f * 16);
            uint32_t h0, l0, h1, l1;
            split_pair(v.x, v.y, h0, l0);
            split_pair(v.z, v.w, h1, l1);
            uint32_t addr = r * BSTRIDE_B + c4 * 8;
            STS64(bh + addr, h0, h1);
            STS64(bl + addr, l0, l1);
        }
    };

    auto compute = [&](int buf) {
        const uint32_t ah = sb + OFF_AHI(buf), al = sb + OFF_ALO(buf);
        const uint32_t bh = sb + OFF_BHI(buf), bl = sb + OFF_BLO(buf);
#pragma unroll
        for (int ks = 0; ks < 2; ks++) {
            const int k0 = ks * 16;
            uint32_t Ah[4][4], Al[4][4], Bh[4][2], Bl[4][2];
#pragma unroll
            for (int mi = 0; mi < 4; mi++) {
                uint32_t addr = (m_base + mi * 16 + a_r_off) * ASTRIDE_B
                              + (k0 + a_c_off) * 2;
                ldsm_x4(ah + addr, Ah[mi]);
                ldsm_x4(al + addr, Al[mi]);
            }
#pragma unroll
            for (int ni = 0; ni < 4; ni++) {
                uint32_t addr = (k0 + b_r_off) * BSTRIDE_B
                              + (n_base + ni * 8) * 2;
                ldsm_x2_trans(bh + addr, Bh[ni]);
                ldsm_x2_trans(bl + addr, Bl[ni]);
            }
#pragma unroll
            for (int mi = 0; mi < 4; mi++)
#pragma unroll
                for (int ni = 0; ni < 4; ni++) {
                    mma_bf16(acc[mi][ni], Ah[mi], Bh[ni]);
                    mma_bf16(acc[mi][ni], Ah[mi], Bl[ni]);
                    mma_bf16(acc[mi][ni], Al[mi], Bh[ni]);
                }
        }
    };

    // ---- prologue: fill 4-stage cp.async ring ----
#pragma unroll
    for (int s = 0; s < NSTAGE; s++) issue_cp(s, s);

    for (int ck = 0; ck < NCHUNK; ck++) {
        CP_WAIT3();                       // this thread's stage ck arrived
        convert(ck, ck & 3, ck & 1);      // reads own stage region, writes bf16 buf
        if (ck + NSTAGE < NCHUNK) issue_cp(ck + NSTAGE, (ck + NSTAGE) & 3);
        else                      CP_COMMIT();   // keep group cadence for WAIT3
        __syncthreads();                  // bf16 buf complete; also spaces buffer reuse
        compute(ck & 1);
    }

    // ---- epilogue: + bias, write ----
    const int g  = lane >> 2;
    const int tq = lane & 3;
#pragma unroll
    for (int mi = 0; mi < 4; mi++) {
        const int r0 = m0 + m_base + mi * 16 + g;
        const int r1 = r0 + 8;
        const float bias0 = g_bias[b][r0];
        const float bias1 = g_bias[b][r1];
        float* p0 = out + ((size_t)b * C_ + r0) * L_ + n0 + n_base + tq * 2;
        float* p1 = out + ((size_t)b * C_ + r1) * L_ + n0 + n_base + tq * 2;
#pragma unroll
        for (int ni = 0; ni < 4; ni++) {
            float2 v0 = make_float2(acc[mi][ni][0] + bias0, acc[mi][ni][1] + bias0);
            float2 v1 = make_float2(acc[mi][ni][2] + bias1, acc[mi][ni][3] + bias1);
            *(float2*)(p0 + ni * 8) = v0;
            *(float2*)(p1 + ni * 8) = v1;
        }
    }
}

// ---------------- launch ----------------
extern "C" void kernel_launch(void* const* d_in, const int* in_sizes, int n_in,
                              void* d_out, int out_size) {
    const float* xs       = (const float*)d_in[0];
    const float* scores   = (const float*)d_in[1];
    const float* expert_w = (const float*)d_in[2];
    const float* expert_b = (const float*)d_in[3];
    float* out = (float*)d_out;

    cudaFuncSetAttribute(moe_mma_kernel,
                         cudaFuncAttributeMaxDynamicSharedMemorySize, SMEM_DYN);

    prep_kernel<<<1, 256>>>(scores, expert_b);

    dim3 grid(L_ / BN, C_ / BM, B_);   // (32, 2, 8) = 512 blocks
    moe_mma_kernel<<<grid, 256, SMEM_DYN>>>(xs, expert_w, out);
}

// round 9
// speedup vs baseline: 1.4886x; 1.4886x over previous
#include <cuda_runtime.h>
#include <cstdint>

// ---------------- problem constants ----------------
#define B_    8
#define K_    8
#define C_    256
#define L_    4096
#define TOPK  4
#define KTOT  1024
#define BM    128
#define BN    128
#define BK    64
#define NCHUNK (KTOT / BK)     // 16

// ---------------- smem layout (bytes from dynamic smem base) ----------------
// A tiles: 128 rows x 64 bf16, padded row stride 72 bf16 = 144 B (9x16B odd -> ldmatrix conflict-free)
// B tiles: 64 rows (k) x 128 bf16 (n), padded stride 136 bf16 = 272 B (17x16B odd)
#define ASTRIDE_B 144
#define BSTRIDE_B 272
#define ATILE_B   (128 * ASTRIDE_B)           // 18432
#define BTILE_B   (64 * BSTRIDE_B)            // 17408
#define BUF_B     (2 * ATILE_B + 2 * BTILE_B) // 71680
#define OFF_AHI(buf) ((buf) * BUF_B + 0)
#define OFF_ALO(buf) ((buf) * BUF_B + ATILE_B)
#define OFF_BHI(buf) ((buf) * BUF_B + 2 * ATILE_B)
#define OFF_BLO(buf) ((buf) * BUF_B + 2 * ATILE_B + BTILE_B)
#define SMEM_DYN  (2 * BUF_B)                  // 143360

// ---------------- helpers ----------------
__device__ __forceinline__ uint32_t smem_u32(const void* p) {
    uint32_t a;
    asm("{ .reg .u64 t; cvta.to.shared.u64 t, %1; cvt.u32.u64 %0, t; }" : "=r"(a) : "l"(p));
    return a;
}

// split x -> (hi = truncate-to-bf16, lo = rn-bf16(x - hi)); pack two elements
__device__ __forceinline__ void split_pair(float x0, float x1,
                                           uint32_t& hi, uint32_t& lo) {
    uint32_t u0 = __float_as_uint(x0), u1 = __float_as_uint(x1);
    hi = __byte_perm(u0, u1, 0x7632);   // {bf16(x1)|bf16(x0)} truncated
    float l0 = x0 - __uint_as_float(u0 & 0xFFFF0000u);
    float l1 = x1 - __uint_as_float(u1 & 0xFFFF0000u);
    asm("cvt.rn.bf16x2.f32 %0, %1, %2;" : "=r"(lo) : "f"(l1), "f"(l0));
}

#define STS64(addr, r0, r1) \
    asm volatile("st.shared.v2.b32 [%0], {%1, %2};" :: "r"(addr), "r"(r0), "r"(r1) : "memory")

__device__ __forceinline__ void ldsm_x4(uint32_t addr, uint32_t* r) {
    asm volatile("ldmatrix.sync.aligned.m8n8.x4.shared.b16 {%0,%1,%2,%3}, [%4];"
                 : "=r"(r[0]), "=r"(r[1]), "=r"(r[2]), "=r"(r[3]) : "r"(addr));
}
__device__ __forceinline__ void ldsm_x2_trans(uint32_t addr, uint32_t* r) {
    asm volatile("ldmatrix.sync.aligned.m8n8.x2.trans.shared.b16 {%0,%1}, [%2];"
                 : "=r"(r[0]), "=r"(r[1]) : "r"(addr));
}
__device__ __forceinline__ void mma_bf16(float* c, const uint32_t* a, const uint32_t* bfr) {
    asm volatile(
        "mma.sync.aligned.m16n8k16.row.col.f32.bf16.bf16.f32 "
        "{%0,%1,%2,%3}, {%4,%5,%6,%7}, {%8,%9}, {%0,%1,%2,%3};"
        : "+f"(c[0]), "+f"(c[1]), "+f"(c[2]), "+f"(c[3])
        : "r"(a[0]), "r"(a[1]), "r"(a[2]), "r"(a[3]), "r"(bfr[0]), "r"(bfr[1]));
}

// ---------------- routing globals ----------------
__device__ int   g_sel[B_][TOPK];
__device__ float g_w[B_][TOPK];
__device__ float g_bias[B_][C_];

__global__ void prep_kernel(const float* __restrict__ scores,
                            const float* __restrict__ expert_b) {
    __shared__ int   s_sel[B_][TOPK];
    __shared__ float s_w[B_][TOPK];
    const int tid = threadIdx.x;
    if (tid < B_) {
        const int b = tid;
        float sc[K_]; bool used[K_];
#pragma unroll
        for (int k = 0; k < K_; k++) { sc[k] = scores[b * K_ + k]; used[k] = false; }
        float sum = 0.f;
#pragma unroll
        for (int j = 0; j < TOPK; j++) {
            int best = 0; float bv = -3.402823466e+38f;
#pragma unroll
            for (int k = 0; k < K_; k++)
                if (!used[k] && sc[k] > bv) { bv = sc[k]; best = k; }  // ties -> lower idx
            used[best] = true; s_sel[b][j] = best; s_w[b][j] = bv; sum += bv;
        }
        const float inv = 1.f / (sum + 1e-8f);
#pragma unroll
        for (int j = 0; j < TOPK; j++) {
            s_w[b][j] *= inv; g_sel[b][j] = s_sel[b][j]; g_w[b][j] = s_w[b][j];
        }
    }
    __syncthreads();
    for (int idx = tid; idx < B_ * C_; idx += blockDim.x) {
        const int b = idx / C_, d = idx % C_;
        float acc = 0.f;
#pragma unroll
        for (int j = 0; j < TOPK; j++)
            acc += s_w[b][j] * expert_b[s_sel[b][j] * C_ + d];
        g_bias[b][d] = acc;
    }
}

// ---------------------------------------------------------------------------
// Tensor-core MoE GEMM via mma.sync (bf16 hi/lo split, 3 terms, fp32 accum).
// Simple stage/compute loop (the empirically fastest structure), BK=64 to
// halve the number of exposed-latency stage phases and barriers.
// out[b](256x4096) = [w_j * W_sel_j](256x1024) @ gathered_xs(1024x4096) + bias
// ---------------------------------------------------------------------------
__global__ __launch_bounds__(256, 1)
void moe_mma_kernel(const float* __restrict__ xs,
                    const float* __restrict__ expert_w,
                    float* __restrict__ out) {
    extern __shared__ char smem[];
    const uint32_t sb = smem_u32(smem);

    const int tid  = threadIdx.x;
    const int wid  = tid >> 5;
    const int lane = tid & 31;
    const int b    = blockIdx.z;
    const int m0   = blockIdx.y * BM;
    const int n0   = blockIdx.x * BN;

    int   sel[TOPK];
    float wv[TOPK];
#pragma unroll
    for (int j = 0; j < TOPK; j++) { sel[j] = g_sel[b][j]; wv[j] = g_w[b][j]; }

    // warp tile: 64 (m) x 32 (n)
    const int wm = wid >> 2, wn = wid & 3;
    const int m_base = wm * 64, n_base = wn * 32;

    float acc[4][4][4];
#pragma unroll
    for (int mi = 0; mi < 4; mi++)
#pragma unroll
        for (int ni = 0; ni < 4; ni++)
#pragma unroll
            for (int r = 0; r < 4; r++) acc[mi][ni][r] = 0.f;

    // ldmatrix address components
    const int lr = lane & 7;
    const int lg = lane >> 3;
    const int a_r_off = (lg & 1) * 8 + lr;
    const int a_c_off = (lg >> 1) * 8;
    const int b_r_off = (lg & 1) * 8 + lr;

    // stage chunk ck (64 K-cols) into buffer buf: LDG -> split -> STS
    auto stage_chunk = [&](int ck, int buf) {
        const int j  = ck >> 2;              // 4 chunks per expert (256/64)
        const int c0 = (ck & 3) * BK;
        const float wj = wv[j];
        const float* asrc = expert_w + ((size_t)sel[j] * C_) * C_ + c0;
        const float* bsrc = xs + (((size_t)b * K_ + sel[j]) * C_ + c0) * L_ + n0;
        const uint32_t ah = sb + OFF_AHI(buf), al = sb + OFF_ALO(buf);
        const uint32_t bh = sb + OFF_BHI(buf), bl = sb + OFF_BLO(buf);

        // A: 128 rows x 16 float4 -> 8 float4/thread
#pragma unroll
        for (int q = 0; q < 8; q++) {
            int f = q * 256 + tid;
            int r = f >> 4, c4 = f & 15;
            float4 v = *(const float4*)(asrc + (size_t)(m0 + r) * C_ + c4 * 4);
            uint32_t h0, l0, h1, l1;
            split_pair(v.x * wj, v.y * wj, h0, l0);
            split_pair(v.z * wj, v.w * wj, h1, l1);
            uint32_t addr = r * ASTRIDE_B + c4 * 8;
            STS64(ah + addr, h0, h1);
            STS64(al + addr, l0, l1);
        }
        // B: 64 rows x 32 float4 -> 8 float4/thread
#pragma unroll
        for (int q = 0; q < 8; q++) {
            int f = q * 256 + tid;
            int r = f >> 5, c4 = f & 31;
            float4 v = *(const float4*)(bsrc + (size_t)r * L_ + c4 * 4);
            uint32_t h0, l0, h1, l1;
            split_pair(v.x, v.y, h0, l0);
            split_pair(v.z, v.w, h1, l1);
            uint32_t addr = r * BSTRIDE_B + c4 * 8;
            STS64(bh + addr, h0, h1);
            STS64(bl + addr, l0, l1);
        }
    };

    auto compute = [&](int buf) {
        const uint32_t ah = sb + OFF_AHI(buf), al = sb + OFF_ALO(buf);
        const uint32_t bh = sb + OFF_BHI(buf), bl = sb + OFF_BLO(buf);
#pragma unroll
        for (int ks = 0; ks < 4; ks++) {
            const int k0 = ks * 16;
            uint32_t Ah[4][4], Al[4][4], Bh[4][2], Bl[4][2];
#pragma unroll
            for (int mi = 0; mi < 4; mi++) {
                uint32_t addr = (m_base + mi * 16 + a_r_off) * ASTRIDE_B
                              + (k0 + a_c_off) * 2;
                ldsm_x4(ah + addr, Ah[mi]);
                ldsm_x4(al + addr, Al[mi]);
            }
#pragma unroll
            for (int ni = 0; ni < 4; ni++) {
                uint32_t addr = (k0 + b_r_off) * BSTRIDE_B
                              + (n_base + ni * 8) * 2;
                ldsm_x2_trans(bh + addr, Bh[ni]);
                ldsm_x2_trans(bl + addr, Bl[ni]);
            }
#pragma unroll
            for (int mi = 0; mi < 4; mi++)
#pragma unroll
                for (int ni = 0; ni < 4; ni++) {
                    mma_bf16(acc[mi][ni], Ah[mi], Bh[ni]);
                    mma_bf16(acc[mi][ni], Ah[mi], Bl[ni]);
                    mma_bf16(acc[mi][ni], Al[mi], Bh[ni]);
                }
        }
    };

    // ---- simple stage/compute loop (empirically fastest structure) ----
    stage_chunk(0, 0);
    __syncthreads();
    for (int ck = 0; ck < NCHUNK; ck++) {
        const int buf = ck & 1;
        compute(buf);
        __syncthreads();
        if (ck + 1 < NCHUNK) {
            stage_chunk(ck + 1, buf ^ 1);
            __syncthreads();
        }
    }

    // ---- epilogue: + bias, write ----
    const int g  = lane >> 2;
    const int tq = lane & 3;
#pragma unroll
    for (int mi = 0; mi < 4; mi++) {
        const int r0 = m0 + m_base + mi * 16 + g;
        const int r1 = r0 + 8;
        const float bias0 = g_bias[b][r0];
        const float bias1 = g_bias[b][r1];
        float* p0 = out + ((size_t)b * C_ + r0) * L_ + n0 + n_base + tq * 2;
        float* p1 = out + ((size_t)b * C_ + r1) * L_ + n0 + n_base + tq * 2;
#pragma unroll
        for (int ni = 0; ni < 4; ni++) {
            float2 v0 = make_float2(acc[mi][ni][0] + bias0, acc[mi][ni][1] + bias0);
            float2 v1 = make_float2(acc[mi][ni][2] + bias1, acc[mi][ni][3] + bias1);
            *(float2*)(p0 + ni * 8) = v0;
            *(float2*)(p1 + ni * 8) = v1;
        }
    }
}

// ---------------- launch ----------------
extern "C" void kernel_launch(void* const* d_in, const int* in_sizes, int n_in,
                              void* d_out, int out_size) {
    const float* xs       = (const float*)d_in[0];
    const float* scores   = (const float*)d_in[1];
    const float* expert_w = (const float*)d_in[2];
    const float* expert_b = (const float*)d_in[3];
    float* out = (float*)d_out;

    cudaFuncSetAttribute(moe_mma_kernel,
                         cudaFuncAttributeMaxDynamicSharedMemorySize, SMEM_DYN);

    prep_kernel<<<1, 256>>>(scores, expert_b);

    dim3 grid(L_ / BN, C_ / BM, B_);   // (32, 2, 8) = 512 blocks
    moe_mma_kernel<<<grid, 256, SMEM_DYN>>>(xs, expert_w, out);
}

// round 10
// speedup vs baseline: 1.5633x; 1.0502x over previous
#include <cuda_runtime.h>
#include <cstdint>

// ---------------- problem constants ----------------
#define B_    8
#define K_    8
#define C_    256
#define L_    4096
#define TOPK  4
#define KTOT  1024
#define BM    128
#define BN    64
#define BK    64
#define NCHUNK (KTOT / BK)     // 16

// ---------------- smem layout (bytes from dynamic smem base) ----------------
// Single buffer (stage/compute are barrier-serialized; double buffer buys nothing).
// A tile: 128 rows x 64 bf16, padded row stride 72 bf16 = 144 B (9x16B odd -> ldmatrix conflict-free)
// B tile: 64 k-rows x 64 bf16, padded stride 72 bf16 = 144 B
#define ASTRIDE_B 144
#define BSTRIDE_B 144
#define ATILE_B   (128 * ASTRIDE_B)           // 18432
#define BTILE_B   (64 * BSTRIDE_B)            // 9216
#define OFF_AHI   0
#define OFF_ALO   ATILE_B
#define OFF_BHI   (2 * ATILE_B)
#define OFF_BLO   (2 * ATILE_B + BTILE_B)
#define SMEM_DYN  (2 * ATILE_B + 2 * BTILE_B) // 55296 -> 2 CTAs/SM

// ---------------- helpers ----------------
__device__ __forceinline__ uint32_t smem_u32(const void* p) {
    uint32_t a;
    asm("{ .reg .u64 t; cvta.to.shared.u64 t, %1; cvt.u32.u64 %0, t; }" : "=r"(a) : "l"(p));
    return a;
}

// split x -> (hi = truncate-to-bf16, lo = rn-bf16(x - hi)); pack two elements
__device__ __forceinline__ void split_pair(float x0, float x1,
                                           uint32_t& hi, uint32_t& lo) {
    uint32_t u0 = __float_as_uint(x0), u1 = __float_as_uint(x1);
    hi = __byte_perm(u0, u1, 0x7632);   // {bf16(x1)|bf16(x0)} truncated
    float l0 = x0 - __uint_as_float(u0 & 0xFFFF0000u);
    float l1 = x1 - __uint_as_float(u1 & 0xFFFF0000u);
    asm("cvt.rn.bf16x2.f32 %0, %1, %2;" : "=r"(lo) : "f"(l1), "f"(l0));
}

#define STS64(addr, r0, r1) \
    asm volatile("st.shared.v2.b32 [%0], {%1, %2};" :: "r"(addr), "r"(r0), "r"(r1) : "memory")

__device__ __forceinline__ void ldsm_x4(uint32_t addr, uint32_t* r) {
    asm volatile("ldmatrix.sync.aligned.m8n8.x4.shared.b16 {%0,%1,%2,%3}, [%4];"
                 : "=r"(r[0]), "=r"(r[1]), "=r"(r[2]), "=r"(r[3]) : "r"(addr));
}
__device__ __forceinline__ void ldsm_x2_trans(uint32_t addr, uint32_t* r) {
    asm volatile("ldmatrix.sync.aligned.m8n8.x2.trans.shared.b16 {%0,%1}, [%2];"
                 : "=r"(r[0]), "=r"(r[1]) : "r"(addr));
}
__device__ __forceinline__ void mma_bf16(float* c, const uint32_t* a, const uint32_t* bfr) {
    asm volatile(
        "mma.sync.aligned.m16n8k16.row.col.f32.bf16.bf16.f32 "
        "{%0,%1,%2,%3}, {%4,%5,%6,%7}, {%8,%9}, {%0,%1,%2,%3};"
        : "+f"(c[0]), "+f"(c[1]), "+f"(c[2]), "+f"(c[3])
        : "r"(a[0]), "r"(a[1]), "r"(a[2]), "r"(a[3]), "r"(bfr[0]), "r"(bfr[1]));
}

// ---------------- routing globals ----------------
__device__ int   g_sel[B_][TOPK];
__device__ float g_w[B_][TOPK];
__device__ float g_bias[B_][C_];

__global__ void prep_kernel(const float* __restrict__ scores,
                            const float* __restrict__ expert_b) {
    __shared__ int   s_sel[B_][TOPK];
    __shared__ float s_w[B_][TOPK];
    const int tid = threadIdx.x;
    if (tid < B_) {
        const int b = tid;
        float sc[K_]; bool used[K_];
#pragma unroll
        for (int k = 0; k < K_; k++) { sc[k] = scores[b * K_ + k]; used[k] = false; }
        float sum = 0.f;
#pragma unroll
        for (int j = 0; j < TOPK; j++) {
            int best = 0; float bv = -3.402823466e+38f;
#pragma unroll
            for (int k = 0; k < K_; k++)
                if (!used[k] && sc[k] > bv) { bv = sc[k]; best = k; }  // ties -> lower idx
            used[best] = true; s_sel[b][j] = best; s_w[b][j] = bv; sum += bv;
        }
        const float inv = 1.f / (sum + 1e-8f);
#pragma unroll
        for (int j = 0; j < TOPK; j++) {
            s_w[b][j] *= inv; g_sel[b][j] = s_sel[b][j]; g_w[b][j] = s_w[b][j];
        }
    }
    __syncthreads();
    for (int idx = tid; idx < B_ * C_; idx += blockDim.x) {
        const int b = idx / C_, d = idx % C_;
        float acc = 0.f;
#pragma unroll
        for (int j = 0; j < TOPK; j++)
            acc += s_w[b][j] * expert_b[s_sel[b][j] * C_ + d];
        g_bias[b][d] = acc;
    }
}

// ---------------------------------------------------------------------------
// Tensor-core MoE GEMM via mma.sync (bf16 hi/lo split, 3 terms, fp32 accum).
// CTA tile 128x64, single smem buffer, 2 CTAs/SM: one CTA's stage phase
// overlaps the co-resident CTA's compute phase (arbiter-level overlap).
// out[b](256x4096) = [w_j * W_sel_j](256x1024) @ gathered_xs(1024x4096) + bias
// ---------------------------------------------------------------------------
__global__ __launch_bounds__(256, 2)
void moe_mma_kernel(const float* __restrict__ xs,
                    const float* __restrict__ expert_w,
                    float* __restrict__ out) {
    extern __shared__ char smem[];
    const uint32_t sb = smem_u32(smem);

    const int tid  = threadIdx.x;
    const int wid  = tid >> 5;
    const int lane = tid & 31;
    const int b    = blockIdx.z;
    const int m0   = blockIdx.y * BM;
    const int n0   = blockIdx.x * BN;

    int   sel[TOPK];
    float wv[TOPK];
#pragma unroll
    for (int j = 0; j < TOPK; j++) { sel[j] = g_sel[b][j]; wv[j] = g_w[b][j]; }

    // warp tile: 32 (m) x 32 (n); 8 warps cover 128x64
    const int wm = wid >> 1, wn = wid & 1;
    const int m_base = wm * 32, n_base = wn * 32;

    float acc[2][4][4];
#pragma unroll
    for (int mi = 0; mi < 2; mi++)
#pragma unroll
        for (int ni = 0; ni < 4; ni++)
#pragma unroll
            for (int r = 0; r < 4; r++) acc[mi][ni][r] = 0.f;

    // ldmatrix address components
    const int lr = lane & 7;
    const int lg = lane >> 3;
    const int a_r_off = (lg & 1) * 8 + lr;
    const int a_c_off = (lg >> 1) * 8;
    const int b_r_off = (lg & 1) * 8 + lr;

    const uint32_t ah = sb + OFF_AHI, al = sb + OFF_ALO;
    const uint32_t bh = sb + OFF_BHI, bl = sb + OFF_BLO;

    // stage chunk ck (64 K-cols) into the single buffer: LDG -> split -> STS
    auto stage_chunk = [&](int ck) {
        const int j  = ck >> 2;              // 4 chunks per expert (256/64)
        const int c0 = (ck & 3) * BK;
        const float wj = wv[j];
        const float* asrc = expert_w + ((size_t)sel[j] * C_) * C_ + c0;
        const float* bsrc = xs + (((size_t)b * K_ + sel[j]) * C_ + c0) * L_ + n0;

        // A: 128 rows x 16 float4 -> 8 float4/thread
#pragma unroll
        for (int q = 0; q < 8; q++) {
            int f = q * 256 + tid;
            int r = f >> 4, c4 = f & 15;
            float4 v = *(const float4*)(asrc + (size_t)(m0 + r) * C_ + c4 * 4);
            uint32_t h0, l0, h1, l1;
            split_pair(v.x * wj, v.y * wj, h0, l0);
            split_pair(v.z * wj, v.w * wj, h1, l1);
            uint32_t addr = r * ASTRIDE_B + c4 * 8;
            STS64(ah + addr, h0, h1);
            STS64(al + addr, l0, l1);
        }
        // B: 64 k-rows x 16 float4 -> 4 float4/thread
#pragma unroll
        for (int q = 0; q < 4; q++) {
            int f = q * 256 + tid;
            int r = f >> 4, c4 = f & 15;
            float4 v = *(const float4*)(bsrc + (size_t)r * L_ + c4 * 4);
            uint32_t h0, l0, h1, l1;
            split_pair(v.x, v.y, h0, l0);
            split_pair(v.z, v.w, h1, l1);
            uint32_t addr = r * BSTRIDE_B + c4 * 8;
            STS64(bh + addr, h0, h1);
            STS64(bl + addr, l0, l1);
        }
    };

    auto compute = [&]() {
#pragma unroll
        for (int ks = 0; ks < 4; ks++) {
            const int k0 = ks * 16;
            uint32_t Ah[2][4], Al[2][4], Bh[4][2], Bl[4][2];
#pragma unroll
            for (int mi = 0; mi < 2; mi++) {
                uint32_t addr = (m_base + mi * 16 + a_r_off) * ASTRIDE_B
                              + (k0 + a_c_off) * 2;
                ldsm_x4(ah + addr, Ah[mi]);
                ldsm_x4(al + addr, Al[mi]);
            }
#pragma unroll
            for (int ni = 0; ni < 4; ni++) {
                uint32_t addr = (k0 + b_r_off) * BSTRIDE_B
                              + (n_base + ni * 8) * 2;
                ldsm_x2_trans(bh + addr, Bh[ni]);
                ldsm_x2_trans(bl + addr, Bl[ni]);
            }
#pragma unroll
            for (int mi = 0; mi < 2; mi++)
#pragma unroll
                for (int ni = 0; ni < 4; ni++) {
                    mma_bf16(acc[mi][ni], Ah[mi], Bh[ni]);
                    mma_bf16(acc[mi][ni], Ah[mi], Bl[ni]);
                    mma_bf16(acc[mi][ni], Al[mi], Bh[ni]);
                }
        }
    };

    // ---- stage/compute loop, single buffer ----
    for (int ck = 0; ck < NCHUNK; ck++) {
        stage_chunk(ck);
        __syncthreads();
        compute();
        __syncthreads();
    }

    // ---- epilogue: + bias, write ----
    const int g  = lane >> 2;
    const int tq = lane & 3;
#pragma unroll
    for (int mi = 0; mi < 2; mi++) {
        const int r0 = m0 + m_base + mi * 16 + g;
        const int r1 = r0 + 8;
        const float bias0 = g_bias[b][r0];
        const float bias1 = g_bias[b][r1];
        float* p0 = out + ((size_t)b * C_ + r0) * L_ + n0 + n_base + tq * 2;
        float* p1 = out + ((size_t)b * C_ + r1) * L_ + n0 + n_base + tq * 2;
#pragma unroll
        for (int ni = 0; ni < 4; ni++) {
            float2 v0 = make_float2(acc[mi][ni][0] + bias0, acc[mi][ni][1] + bias0);
            float2 v1 = make_float2(acc[mi][ni][2] + bias1, acc[mi][ni][3] + bias1);
            *(float2*)(p0 + ni * 8) = v0;
            *(float2*)(p1 + ni * 8) = v1;
        }
    }
}

// ---------------- launch ----------------
extern "C" void kernel_launch(void* const* d_in, const int* in_sizes, int n_in,
                              void* d_out, int out_size) {
    const float* xs       = (const float*)d_in[0];
    const float* scores   = (const float*)d_in[1];
    const float* expert_w = (const float*)d_in[2];
    const float* expert_b = (const float*)d_in[3];
    float* out = (float*)d_out;

    cudaFuncSetAttribute(moe_mma_kernel,
                         cudaFuncAttributeMaxDynamicSharedMemorySize, SMEM_DYN);

    prep_kernel<<<1, 256>>>(scores, expert_b);

    dim3 grid(L_ / BN, C_ / BM, B_);   // (64, 2, 8) = 1024 blocks
    moe_mma_kernel<<<grid, 256, SMEM_DYN>>>(xs, expert_w, out);
}